// round 15
// baseline (speedup 1.0000x reference)
#include <cuda_runtime.h>
#include <cuda.h>
#include <cuda_fp16.h>
#include <cstdint>

#define L_SEQ 1024
#define C_S   1024
#define DD    32      // inner dim
#define CZ    128     // pairwise dim
#define I_PER_CTA 16
#define JT    64      // j columns per phase2 CTA

#define BUFB  32768   // one staging buffer (64 rows x 512B)
#define NBUF  2
#define KSH_OFF  (NBUF * BUFB)                       // f16x2 k pairs: 16 i x 16
#define SMEM2_BYTES (KSH_OFF + I_PER_CTA * 16 * 4)   // 66560

// Scratch (allocation-free rule: __device__ globals)
__device__ float g_s[L_SEQ * C_S];    // normalized rows (4MB)
__device__ float g_q[L_SEQ * DD];
__device__ float g_k[L_SEQ * DD];
__device__ float g_Ak[L_SEQ * CZ];

__device__ __forceinline__ uint32_t swz(uint32_t b) {
    return b ^ ((b >> 3) & 0x70);
}
__device__ __forceinline__ unsigned packh2(float lo, float hi) {
    __half2 h = __floats2half2_rn(lo, hi);
    return *reinterpret_cast<unsigned*>(&h);
}
__device__ __forceinline__ unsigned hfma2u(unsigned a, unsigned b, unsigned c) {
    __half2 r = __hfma2(*reinterpret_cast<__half2*>(&a),
                        *reinterpret_cast<__half2*>(&b),
                        *reinterpret_cast<__half2*>(&c));
    return *reinterpret_cast<unsigned*>(&r);
}

// ---------------------------------------------------------------------------
// Phase 1a: LayerNorm -> g_s. One CTA per row; pure streaming.
// ---------------------------------------------------------------------------
__global__ __launch_bounds__(256) void ln_kernel(
    const float* __restrict__ x,
    const float* __restrict__ lnw, const float* __restrict__ lnb)
{
    __shared__ float red[16];
    const int row  = blockIdx.x;
    const int tid  = threadIdx.x;
    const int lane = tid & 31;
    const int wid  = tid >> 5;

    const float4 xv = ((const float4*)(x + (size_t)row * C_S))[tid];
    float sum = xv.x + xv.y + xv.z + xv.w;
    float sq  = fmaf(xv.x, xv.x, fmaf(xv.y, xv.y, fmaf(xv.z, xv.z, xv.w * xv.w)));
#pragma unroll
    for (int o = 16; o; o >>= 1) {
        sum += __shfl_xor_sync(~0u, sum, o);
        sq  += __shfl_xor_sync(~0u, sq,  o);
    }
    if (lane == 0) { red[wid] = sum; red[8 + wid] = sq; }
    __syncthreads();
    sum = 0.f; sq = 0.f;
#pragma unroll
    for (int w = 0; w < 8; w++) { sum += red[w]; sq += red[8 + w]; }
    const float mu   = sum * (1.0f / C_S);
    const float var  = sq * (1.0f / C_S) - mu * mu;
    const float rstd = rsqrtf(var + 1e-5f);

    const float4 wv = ((const float4*)lnw)[tid];
    const float4 bv = ((const float4*)lnb)[tid];
    float4 sv;
    sv.x = (xv.x - mu) * rstd * wv.x + bv.x;
    sv.y = (xv.y - mu) * rstd * wv.y + bv.y;
    sv.z = (xv.z - mu) * rstd * wv.z + bv.z;
    sv.w = (xv.w - mu) * rstd * wv.w + bv.w;
    ((float4*)g_s)[(size_t)row * (C_S / 4) + tid] = sv;
}

// ---------------------------------------------------------------------------
// Phase 1b: projection g_s @ pw^T -> q,k. Grid (128 row-tiles, 2 d-groups).
// Each warp computes 4 d's fused in ONE pass over the smem row tile.
// ---------------------------------------------------------------------------
__global__ __launch_bounds__(256) void proj_kernel(
    const float* __restrict__ pw, const float* __restrict__ pb)
{
    __shared__ float4 s4[8][C_S / 4];        // 32KB row tile

    const int tid  = threadIdx.x;
    const int lane = tid & 31;
    const int wid  = tid >> 5;
    const int row0 = blockIdx.x * 8;
    const int dbase = blockIdx.y * 32 + wid * 4;

#pragma unroll
    for (int r = 0; r < 8; r++)
        s4[r][tid] = ((const float4*)g_s)[(size_t)(row0 + r) * (C_S / 4) + tid];
    __syncthreads();

    const float4* wr0 = (const float4*)(pw + (size_t)(dbase + 0) * C_S) + lane;
    const float4* wr1 = (const float4*)(pw + (size_t)(dbase + 1) * C_S) + lane;
    const float4* wr2 = (const float4*)(pw + (size_t)(dbase + 2) * C_S) + lane;
    const float4* wr3 = (const float4*)(pw + (size_t)(dbase + 3) * C_S) + lane;

    float acc[4][8];
#pragma unroll
    for (int dd = 0; dd < 4; dd++)
#pragma unroll
        for (int r = 0; r < 8; r++) acc[dd][r] = 0.f;

#pragma unroll
    for (int cc = 0; cc < 8; cc++) {
        float4 w4[4];
        w4[0] = wr0[32 * cc];
        w4[1] = wr1[32 * cc];
        w4[2] = wr2[32 * cc];
        w4[3] = wr3[32 * cc];
#pragma unroll
        for (int r = 0; r < 8; r++) {
            const float4 v = s4[r][lane + 32 * cc];
#pragma unroll
            for (int dd = 0; dd < 4; dd++) {
                acc[dd][r] = fmaf(v.x, w4[dd].x, fmaf(v.y, w4[dd].y,
                             fmaf(v.z, w4[dd].z, fmaf(v.w, w4[dd].w, acc[dd][r]))));
            }
        }
    }

#pragma unroll
    for (int o = 16; o; o >>= 1) {
#pragma unroll
        for (int dd = 0; dd < 4; dd++)
#pragma unroll
            for (int r = 0; r < 8; r++)
                acc[dd][r] += __shfl_xor_sync(~0u, acc[dd][r], o);
    }
    if (lane == 0) {
#pragma unroll
        for (int dd = 0; dd < 4; dd++) {
            const int dg = dbase + dd;
            const float pbd = pb[dg];
#pragma unroll
            for (int r = 0; r < 8; r++) {
                const float val = acc[dd][r] + pbd;
                if (dg < DD) g_q[(row0 + r) * DD + dg]        = val;
                else         g_k[(row0 + r) * DD + (dg - DD)] = val;
            }
        }
    }
}

// ---------------------------------------------------------------------------
// Phase 1c: Ak[i,z] = sum_d k[i,d] * W2[z,d] via padded smem W2 table.
// Grid 256 CTAs x 4 rows.
// ---------------------------------------------------------------------------
__global__ __launch_bounds__(256) void akk_kernel(
    const float* __restrict__ ow)
{
    __shared__ float ow2s[CZ * (DD + 1)];
    __shared__ float ksm[4 * DD];

    const int tid  = threadIdx.x;
    const int row0 = blockIdx.x * 4;

    for (int it = tid; it < CZ * DD; it += 256) {
        const int z = it >> 5, d = it & 31;
        ow2s[z * (DD + 1) + d] = ow[z * (2 * DD) + DD + d];
    }
    if (tid < 4 * DD) ksm[tid] = g_k[row0 * DD + tid];
    __syncthreads();

#pragma unroll
    for (int hh = 0; hh < 2; hh++) {
        const int idx = tid + 256 * hh;
        const int r = idx >> 7, z = idx & 127;
        float acc = 0.f;
#pragma unroll
        for (int d = 0; d < DD; d++)
            acc = fmaf(ksm[r * DD + d], ow2s[z * (DD + 1) + d], acc);
        g_Ak[(row0 + r) * CZ + z] = acc;
    }
}

// ---------------------------------------------------------------------------
// Phase 2: fp16 m16n8k16 mma (M=z, N=j), fp32 accum, SW128 staging + TMA store.
// 3 CTAs/SM, bias prefetch pipeline. [R14 proven — unchanged]
// ---------------------------------------------------------------------------
extern __shared__ char smem_dyn[];

__global__ __launch_bounds__(256, 3) void phase2_kernel(
    const __grid_constant__ CUtensorMap tmap,
    const float* __restrict__ ow, const float* __restrict__ ob)
{
    unsigned* ksh = (unsigned*)(smem_dyn + KSH_OFF);   // [16 i][16 d-pairs] f16x2
    unsigned* qsh = (unsigned*)smem_dyn;               // [64 j][20] pairs (temp buf0)

    uint32_t smem_u32;
    asm("{ .reg .u64 t; cvta.to.shared.u64 t, %1; cvt.u32.u64 %0, t; }"
        : "=r"(smem_u32) : "l"(smem_dyn));

    const int tid  = threadIdx.x;
    const int lane = tid & 31;
    const int wid  = tid >> 5;
    const int l4   = lane & 3;
    const int lg   = lane >> 2;
    const int jbase = blockIdx.x * JT;
    const int ibase = blockIdx.y * I_PER_CTA;

    // ---- one-time staging: q pairs (f16x2, pad-20 rows) and k pairs ----
#pragma unroll
    for (int m = 0; m < 4; m++) {
        const int it = tid + 256 * m;                  // 1024 q pairs
        const int j = it >> 4, p = it & 15;
        const float* qp = g_q + (size_t)(jbase + j) * DD + 2 * p;
        qsh[j * 20 + p] = packh2(qp[0], qp[1]);
    }
    {
        const int ii = tid >> 4, p = tid & 15;         // 256 k pairs
        const float* kp = g_k + (size_t)(ibase + ii) * DD + 2 * p;
        ksh[tid] = packh2(kp[0], kp[1]);
    }

    const int z0 = wid * 16 + lg;            // global z row; +8 for upper

    // ---- W1/W2 as f16x2 fragment pairs, register resident ----
    unsigned w1h[2][4], w2h[2][4];
#pragma unroll
    for (int kk = 0; kk < 2; kk++) {
        const int d0 = 16 * kk + 2 * l4;
        const float* r0 = ow + (size_t)z0 * (2 * DD);
        const float* r1 = ow + (size_t)(z0 + 8) * (2 * DD);
        w1h[kk][0] = packh2(r0[d0],      r0[d0 + 1]);
        w1h[kk][1] = packh2(r1[d0],      r1[d0 + 1]);
        w1h[kk][2] = packh2(r0[d0 + 8],  r0[d0 + 9]);
        w1h[kk][3] = packh2(r1[d0 + 8],  r1[d0 + 9]);
        w2h[kk][0] = packh2(r0[DD + d0],     r0[DD + d0 + 1]);
        w2h[kk][1] = packh2(r1[DD + d0],     r1[DD + d0 + 1]);
        w2h[kk][2] = packh2(r0[DD + d0 + 8], r0[DD + d0 + 9]);
        w2h[kk][3] = packh2(r1[DD + d0 + 8], r1[DD + d0 + 9]);
    }
    const float ob0 = ob[z0];
    const float ob1 = ob[z0 + 8];

    __syncthreads();   // qsh/ksh staged

    // ---- q B fragments: bq[n][0..3] = {kk0 b0, kk0 b1, kk1 b0, kk1 b1} ----
    unsigned bq[8][4];
#pragma unroll
    for (int n = 0; n < 8; n++) {
        const unsigned* qrow = qsh + (8 * n + lg) * 20;
        bq[n][0] = qrow[l4];
        bq[n][1] = qrow[l4 + 4];
        bq[n][2] = qrow[l4 + 8];
        bq[n][3] = qrow[l4 + 12];
    }
    __syncthreads();   // qsh reads done; buf0 may be overwritten

    // staging offsets (conflict-free SW128 pattern)
    const uint32_t p0 = swz((uint32_t)(2 * l4) * 512 + (uint32_t)z0 * 4);
    const uint32_t p1 = p0 ^ 0x240;          // j+1
    const uint32_t p2 = p0 ^ 32;             // z0+8
    const uint32_t p3 = p0 ^ 0x260;          // j+1, z0+8

    const float* akp = g_Ak + (size_t)ibase * CZ + z0;

    // bias prefetch pipeline (registers)
    float nb0 = __ldg(akp);
    float nb1 = __ldg(akp + 8);

#pragma unroll 1
    for (int ii = 0; ii < I_PER_CTA; ii++) {
        char* stg = smem_dyn + (ii & 1) * BUFB;

        const float bias0 = ob0 - nb0;
        const float bias1 = ob1 - nb1;
        if (ii + 1 < I_PER_CTA) {
            nb0 = __ldg(akp + (ii + 1) * CZ);
            nb1 = __ldg(akp + (ii + 1) * CZ + 8);
        }

        // build Ghat A fragments: 8 HFMA2 from f16x2 k pairs (broadcast LDS)
        unsigned afr[2][4];
        {
            const unsigned* kp = ksh + ii * 16;
            const unsigned k00 = kp[l4],      k01 = kp[l4 + 4];
            const unsigned k10 = kp[l4 + 8],  k11 = kp[l4 + 12];
            afr[0][0] = hfma2u(k00, w1h[0][0], w2h[0][0]);
            afr[0][1] = hfma2u(k00, w1h[0][1], w2h[0][1]);
            afr[0][2] = hfma2u(k01, w1h[0][2], w2h[0][2]);
            afr[0][3] = hfma2u(k01, w1h[0][3], w2h[0][3]);
            afr[1][0] = hfma2u(k10, w1h[1][0], w2h[1][0]);
            afr[1][1] = hfma2u(k10, w1h[1][1], w2h[1][1]);
            afr[1][2] = hfma2u(k11, w1h[1][2], w2h[1][2]);
            afr[1][3] = hfma2u(k11, w1h[1][3], w2h[1][3]);
        }

#pragma unroll
        for (int n = 0; n < 8; n++) {
            float c0 = bias0, c1 = bias0, c2 = bias1, c3 = bias1;
#pragma unroll
            for (int kk = 0; kk < 2; kk++) {
                asm volatile(
                    "mma.sync.aligned.m16n8k16.row.col.f32.f16.f16.f32 "
                    "{%0,%1,%2,%3},{%4,%5,%6,%7},{%8,%9},{%0,%1,%2,%3};"
                    : "+f"(c0), "+f"(c1), "+f"(c2), "+f"(c3)
                    : "r"(afr[kk][0]), "r"(afr[kk][1]), "r"(afr[kk][2]), "r"(afr[kk][3]),
                      "r"(bq[n][2 * kk]), "r"(bq[n][2 * kk + 1]));
            }
            const uint32_t nb = (uint32_t)(n << 12);   // j += 8 -> +4096B
            *(float*)(stg + p0 + nb) = c0;
            *(float*)(stg + p1 + nb) = c1;
            *(float*)(stg + p2 + nb) = c2;
            *(float*)(stg + p3 + nb) = c3;
        }

        asm volatile("fence.proxy.async.shared::cta;" ::: "memory");
        __syncthreads();   // all STS for this i visible

        if (tid == 0) {
            const uint32_t sbase = smem_u32 + (ii & 1) * BUFB;
            const int row = (ibase + ii) * L_SEQ + jbase;
            asm volatile(
                "cp.async.bulk.tensor.3d.global.shared::cta.tile.bulk_group "
                "[%0, {%1, %2, %3}], [%4];"
                :: "l"(&tmap), "r"(0), "r"(0), "r"(row), "r"(sbase) : "memory");
            asm volatile("cp.async.bulk.commit_group;" ::: "memory");
            // <=1 group pending: the other buffer is free for ii+1
            asm volatile("cp.async.bulk.wait_group.read 1;" ::: "memory");
        }
        __syncthreads();
    }

    if (tid == 0)
        asm volatile("cp.async.bulk.wait_group 0;" ::: "memory");
}

// ---------------------------------------------------------------------------
typedef CUresult (*EncodeFn)(
    CUtensorMap*, CUtensorMapDataType, cuuint32_t, void*,
    const cuuint64_t*, const cuuint64_t*, const cuuint32_t*, const cuuint32_t*,
    CUtensorMapInterleave, CUtensorMapSwizzle, CUtensorMapL2promotion,
    CUtensorMapFloatOOBfill);

extern "C" void kernel_launch(void* const* d_in, const int* in_sizes, int n_in,
                              void* d_out, int out_size)
{
    const float* x   = (const float*)d_in[0];
    const float* lnw = (const float*)d_in[1];
    const float* lnb = (const float*)d_in[2];
    const float* pw  = (const float*)d_in[3];
    const float* pb  = (const float*)d_in[4];
    const float* ow  = (const float*)d_in[5];
    const float* ob  = (const float*)d_in[6];

    // Output viewed as [row = i*L+j : 1M][chunk : 4][32 f32]; one 32KB box/tile.
    CUtensorMap tmap;
    {
        void* fn = nullptr;
        cudaDriverEntryPointQueryResult qr;
        cudaGetDriverEntryPoint("cuTensorMapEncodeTiled", &fn,
                                cudaEnableDefault, &qr);
        EncodeFn enc = (EncodeFn)fn;
        cuuint64_t dims[3]    = {32, 4, (cuuint64_t)L_SEQ * L_SEQ};
        cuuint64_t strides[2] = {128, 512};          // bytes
        cuuint32_t box[3]     = {32, 4, JT};
        cuuint32_t es[3]      = {1, 1, 1};
        enc(&tmap, CU_TENSOR_MAP_DATA_TYPE_FLOAT32, 3, d_out,
            dims, strides, box, es,
            CU_TENSOR_MAP_INTERLEAVE_NONE, CU_TENSOR_MAP_SWIZZLE_128B,
            CU_TENSOR_MAP_L2_PROMOTION_NONE, CU_TENSOR_MAP_FLOAT_OOB_FILL_NONE);
    }

    cudaFuncSetAttribute(phase2_kernel,
                         cudaFuncAttributeMaxDynamicSharedMemorySize, SMEM2_BYTES);

    ln_kernel  <<<L_SEQ, 256>>>(x, lnw, lnb);
    proj_kernel<<<dim3(L_SEQ / 8, 2), 256>>>(pw, pb);
    akk_kernel <<<L_SEQ / 4, 256>>>(ow);
    phase2_kernel<<<dim3(L_SEQ / JT, L_SEQ / I_PER_CTA), 256, SMEM2_BYTES>>>(
        tmap, ow, ob);
}

// round 17
// speedup vs baseline: 1.0375x; 1.0375x over previous
#include <cuda_runtime.h>
#include <cuda.h>
#include <cuda_fp16.h>
#include <cstdint>

#define L_SEQ 1024
#define C_S   1024
#define DD    32      // inner dim
#define CZ    128     // pairwise dim
#define I_PER_CTA 16
#define JT    64      // j columns per phase2 CTA
#define R1    4       // rows per CTA in phase1 (512 CTAs -> 1.16 waves)

#define BUFB  32768   // one staging buffer (64 rows x 512B)
#define NBUF  2
#define KSH_OFF  (NBUF * BUFB)                       // f16x2 k pairs: 16 i x 16
#define SMEM2_BYTES (KSH_OFF + I_PER_CTA * 16 * 4)   // 66560

// Scratch (allocation-free rule: __device__ globals)
__device__ float g_q[L_SEQ * DD];
__device__ float g_k[L_SEQ * DD];
__device__ float g_Ak[L_SEQ * CZ];

__device__ __forceinline__ uint32_t swz(uint32_t b) {
    return b ^ ((b >> 3) & 0x70);
}
__device__ __forceinline__ unsigned packh2(float lo, float hi) {
    __half2 h = __floats2half2_rn(lo, hi);
    return *reinterpret_cast<unsigned*>(&h);
}
__device__ __forceinline__ unsigned hfma2u(unsigned a, unsigned b, unsigned c) {
    __half2 r = __hfma2(*reinterpret_cast<__half2*>(&a),
                        *reinterpret_cast<__half2*>(&b),
                        *reinterpret_cast<__half2*>(&c));
    return *reinterpret_cast<unsigned*>(&r);
}

// ---------------------------------------------------------------------------
// Phase 1: LayerNorm + projection -> q,k [L,32]; Ak[i,z] = sum_d k[i,d]*W2[z,d]
// Grid (L/R1, 2): blockIdx.y selects the d-half (0 -> q, 1 -> k + Ak).
// R1=4: 512 CTAs. ow2s has its OWN smem array (R16 bug: reusing s4 overflowed
// 16384B s4 with a 16896B table, corrupting red/qk).
// ---------------------------------------------------------------------------
__global__ __launch_bounds__(256) void phase1_kernel(
    const float* __restrict__ x,
    const float* __restrict__ lnw, const float* __restrict__ lnb,
    const float* __restrict__ pw,  const float* __restrict__ pb,
    const float* __restrict__ ow)
{
    __shared__ float4 s4[R1][C_S / 4];       // 16KB normalized rows
    __shared__ float red[2][R1][8];
    __shared__ float qk[R1][DD];
    __shared__ float ow2s[CZ * (DD + 1)];    // 16.9KB padded W2 table (dedicated!)

    const int tid  = threadIdx.x;
    const int lane = tid & 31;
    const int wid  = tid >> 5;
    const int row0 = blockIdx.x * R1;
    const int h    = blockIdx.y;             // 0: q half, 1: k half

    // preload W2 table early (k-half CTAs only); covered by syncs below
    if (h == 1) {
        for (int it = tid; it < CZ * DD; it += 256) {
            const int z = it >> 5, d = it & 31;
            ow2s[z * (DD + 1) + d] = ow[z * (2 * DD) + DD + d];
        }
    }

    // ---- LayerNorm for 4 rows ----
    {
        float4 xv[R1];
        float sum[R1], sq[R1];
#pragma unroll
        for (int r = 0; r < R1; r++) {
            xv[r]  = ((const float4*)(x + (size_t)(row0 + r) * C_S))[tid];
            sum[r] = xv[r].x + xv[r].y + xv[r].z + xv[r].w;
            sq[r]  = fmaf(xv[r].x, xv[r].x, fmaf(xv[r].y, xv[r].y,
                     fmaf(xv[r].z, xv[r].z, xv[r].w * xv[r].w)));
        }
#pragma unroll
        for (int o = 16; o; o >>= 1) {
#pragma unroll
            for (int r = 0; r < R1; r++) {
                sum[r] += __shfl_xor_sync(~0u, sum[r], o);
                sq[r]  += __shfl_xor_sync(~0u, sq[r],  o);
            }
        }
        if (lane == 0) {
#pragma unroll
            for (int r = 0; r < R1; r++) { red[0][r][wid] = sum[r]; red[1][r][wid] = sq[r]; }
        }
        __syncthreads();

        const float4 wv = ((const float4*)lnw)[tid];
        const float4 bv = ((const float4*)lnb)[tid];
#pragma unroll
        for (int r = 0; r < R1; r++) {
            float s = 0.f, q = 0.f;
#pragma unroll
            for (int w = 0; w < 8; w++) { s += red[0][r][w]; q += red[1][r][w]; }
            const float mu   = s * (1.0f / C_S);
            const float var  = q * (1.0f / C_S) - mu * mu;
            const float rstd = rsqrtf(var + 1e-5f);
            float4 sv;
            sv.x = (xv[r].x - mu) * rstd * wv.x + bv.x;
            sv.y = (xv[r].y - mu) * rstd * wv.y + bv.y;
            sv.z = (xv[r].z - mu) * rstd * wv.z + bv.z;
            sv.w = (xv[r].w - mu) * rstd * wv.w + bv.w;
            s4[r][tid] = sv;
        }
    }
    __syncthreads();

    // ---- projection: warp w computes d = w*4 .. w*4+3 for 4 rows, fused ----
    {
        const int dbase = h * DD + wid * 4;
        const float4* wr0 = (const float4*)(pw + (size_t)(dbase + 0) * C_S) + lane;
        const float4* wr1 = (const float4*)(pw + (size_t)(dbase + 1) * C_S) + lane;
        const float4* wr2 = (const float4*)(pw + (size_t)(dbase + 2) * C_S) + lane;
        const float4* wr3 = (const float4*)(pw + (size_t)(dbase + 3) * C_S) + lane;

        float acc[4][R1];
#pragma unroll
        for (int dd = 0; dd < 4; dd++)
#pragma unroll
            for (int r = 0; r < R1; r++) acc[dd][r] = 0.f;

#pragma unroll
        for (int cc = 0; cc < 8; cc++) {
            float4 w4[4];
            w4[0] = wr0[32 * cc];
            w4[1] = wr1[32 * cc];
            w4[2] = wr2[32 * cc];
            w4[3] = wr3[32 * cc];
#pragma unroll
            for (int r = 0; r < R1; r++) {
                const float4 v = s4[r][lane + 32 * cc];
#pragma unroll
                for (int dd = 0; dd < 4; dd++) {
                    acc[dd][r] = fmaf(v.x, w4[dd].x, fmaf(v.y, w4[dd].y,
                                 fmaf(v.z, w4[dd].z, fmaf(v.w, w4[dd].w, acc[dd][r]))));
                }
            }
        }

#pragma unroll
        for (int o = 16; o; o >>= 1) {
#pragma unroll
            for (int dd = 0; dd < 4; dd++)
#pragma unroll
                for (int r = 0; r < R1; r++)
                    acc[dd][r] += __shfl_xor_sync(~0u, acc[dd][r], o);
        }
        if (lane == 0) {
#pragma unroll
            for (int dd = 0; dd < 4; dd++) {
                const float pbd = pb[dbase + dd];
#pragma unroll
                for (int r = 0; r < R1; r++)
                    qk[r][wid * 4 + dd] = acc[dd][r] + pbd;
            }
        }
    }
    __syncthreads();

    // ---- write q or k (4 rows x 32 = 128 values) ----
    if (tid < R1 * DD) {
        const int r = tid >> 5, v = tid & 31;
        if (h == 0) g_q[(row0 + r) * DD + v] = qk[r][v];
        else        g_k[(row0 + r) * DD + v] = qk[r][v];
    }

    // ---- Ak (k half only) via dedicated padded W2 table ----
    if (h == 1) {
#pragma unroll
        for (int hh = 0; hh < 2; hh++) {
            const int idx = tid + 256 * hh;
            const int r = idx >> 7, z = idx & 127;
            float acc = 0.f;
#pragma unroll
            for (int d = 0; d < DD; d++)
                acc = fmaf(qk[r][d], ow2s[z * (DD + 1) + d], acc);
            g_Ak[(row0 + r) * CZ + z] = acc;
        }
    }
}

// ---------------------------------------------------------------------------
// Phase 2: fp16 m16n8k16 mma (M=z, N=j), fp32 accum, SW128 staging + TMA store.
// 3 CTAs/SM, bias prefetch pipeline. [R14 proven — byte-identical, untouched]
// ---------------------------------------------------------------------------
extern __shared__ char smem_dyn[];

__global__ __launch_bounds__(256, 3) void phase2_kernel(
    const __grid_constant__ CUtensorMap tmap,
    const float* __restrict__ ow, const float* __restrict__ ob)
{
    unsigned* ksh = (unsigned*)(smem_dyn + KSH_OFF);   // [16 i][16 d-pairs] f16x2
    unsigned* qsh = (unsigned*)smem_dyn;               // [64 j][20] pairs (temp buf0)

    uint32_t smem_u32;
    asm("{ .reg .u64 t; cvta.to.shared.u64 t, %1; cvt.u32.u64 %0, t; }"
        : "=r"(smem_u32) : "l"(smem_dyn));

    const int tid  = threadIdx.x;
    const int lane = tid & 31;
    const int wid  = tid >> 5;
    const int l4   = lane & 3;
    const int lg   = lane >> 2;
    const int jbase = blockIdx.x * JT;
    const int ibase = blockIdx.y * I_PER_CTA;

    // ---- one-time staging: q pairs (f16x2, pad-20 rows) and k pairs ----
#pragma unroll
    for (int m = 0; m < 4; m++) {
        const int it = tid + 256 * m;                  // 1024 q pairs
        const int j = it >> 4, p = it & 15;
        const float* qp = g_q + (size_t)(jbase + j) * DD + 2 * p;
        qsh[j * 20 + p] = packh2(qp[0], qp[1]);
    }
    {
        const int ii = tid >> 4, p = tid & 15;         // 256 k pairs
        const float* kp = g_k + (size_t)(ibase + ii) * DD + 2 * p;
        ksh[tid] = packh2(kp[0], kp[1]);
    }

    const int z0 = wid * 16 + lg;            // global z row; +8 for upper

    // ---- W1/W2 as f16x2 fragment pairs, register resident ----
    unsigned w1h[2][4], w2h[2][4];
#pragma unroll
    for (int kk = 0; kk < 2; kk++) {
        const int d0 = 16 * kk + 2 * l4;
        const float* r0 = ow + (size_t)z0 * (2 * DD);
        const float* r1 = ow + (size_t)(z0 + 8) * (2 * DD);
        w1h[kk][0] = packh2(r0[d0],      r0[d0 + 1]);
        w1h[kk][1] = packh2(r1[d0],      r1[d0 + 1]);
        w1h[kk][2] = packh2(r0[d0 + 8],  r0[d0 + 9]);
        w1h[kk][3] = packh2(r1[d0 + 8],  r1[d0 + 9]);
        w2h[kk][0] = packh2(r0[DD + d0],     r0[DD + d0 + 1]);
        w2h[kk][1] = packh2(r1[DD + d0],     r1[DD + d0 + 1]);
        w2h[kk][2] = packh2(r0[DD + d0 + 8], r0[DD + d0 + 9]);
        w2h[kk][3] = packh2(r1[DD + d0 + 8], r1[DD + d0 + 9]);
    }
    const float ob0 = ob[z0];
    const float ob1 = ob[z0 + 8];

    __syncthreads();   // qsh/ksh staged

    // ---- q B fragments: bq[n][0..3] = {kk0 b0, kk0 b1, kk1 b0, kk1 b1} ----
    unsigned bq[8][4];
#pragma unroll
    for (int n = 0; n < 8; n++) {
        const unsigned* qrow = qsh + (8 * n + lg) * 20;
        bq[n][0] = qrow[l4];
        bq[n][1] = qrow[l4 + 4];
        bq[n][2] = qrow[l4 + 8];
        bq[n][3] = qrow[l4 + 12];
    }
    __syncthreads();   // qsh reads done; buf0 may be overwritten

    // staging offsets (conflict-free SW128 pattern)
    const uint32_t p0 = swz((uint32_t)(2 * l4) * 512 + (uint32_t)z0 * 4);
    const uint32_t p1 = p0 ^ 0x240;          // j+1
    const uint32_t p2 = p0 ^ 32;             // z0+8
    const uint32_t p3 = p0 ^ 0x260;          // j+1, z0+8

    const float* akp = g_Ak + (size_t)ibase * CZ + z0;

    // bias prefetch pipeline (registers)
    float nb0 = __ldg(akp);
    float nb1 = __ldg(akp + 8);

#pragma unroll 1
    for (int ii = 0; ii < I_PER_CTA; ii++) {
        char* stg = smem_dyn + (ii & 1) * BUFB;

        const float bias0 = ob0 - nb0;
        const float bias1 = ob1 - nb1;
        if (ii + 1 < I_PER_CTA) {
            nb0 = __ldg(akp + (ii + 1) * CZ);
            nb1 = __ldg(akp + (ii + 1) * CZ + 8);
        }

        // build Ghat A fragments: 8 HFMA2 from f16x2 k pairs (broadcast LDS)
        unsigned afr[2][4];
        {
            const unsigned* kp = ksh + ii * 16;
            const unsigned k00 = kp[l4],      k01 = kp[l4 + 4];
            const unsigned k10 = kp[l4 + 8],  k11 = kp[l4 + 12];
            afr[0][0] = hfma2u(k00, w1h[0][0], w2h[0][0]);
            afr[0][1] = hfma2u(k00, w1h[0][1], w2h[0][1]);
            afr[0][2] = hfma2u(k01, w1h[0][2], w2h[0][2]);
            afr[0][3] = hfma2u(k01, w1h[0][3], w2h[0][3]);
            afr[1][0] = hfma2u(k10, w1h[1][0], w2h[1][0]);
            afr[1][1] = hfma2u(k10, w1h[1][1], w2h[1][1]);
            afr[1][2] = hfma2u(k11, w1h[1][2], w2h[1][2]);
            afr[1][3] = hfma2u(k11, w1h[1][3], w2h[1][3]);
        }

#pragma unroll
        for (int n = 0; n < 8; n++) {
            float c0 = bias0, c1 = bias0, c2 = bias1, c3 = bias1;
#pragma unroll
            for (int kk = 0; kk < 2; kk++) {
                asm volatile(
                    "mma.sync.aligned.m16n8k16.row.col.f32.f16.f16.f32 "
                    "{%0,%1,%2,%3},{%4,%5,%6,%7},{%8,%9},{%0,%1,%2,%3};"
                    : "+f"(c0), "+f"(c1), "+f"(c2), "+f"(c3)
                    : "r"(afr[kk][0]), "r"(afr[kk][1]), "r"(afr[kk][2]), "r"(afr[kk][3]),
                      "r"(bq[n][2 * kk]), "r"(bq[n][2 * kk + 1]));
            }
            const uint32_t nb = (uint32_t)(n << 12);   // j += 8 -> +4096B
            *(float*)(stg + p0 + nb) = c0;
            *(float*)(stg + p1 + nb) = c1;
            *(float*)(stg + p2 + nb) = c2;
            *(float*)(stg + p3 + nb) = c3;
        }

        asm volatile("fence.proxy.async.shared::cta;" ::: "memory");
        __syncthreads();   // all STS for this i visible

        if (tid == 0) {
            const uint32_t sbase = smem_u32 + (ii & 1) * BUFB;
            const int row = (ibase + ii) * L_SEQ + jbase;
            asm volatile(
                "cp.async.bulk.tensor.3d.global.shared::cta.tile.bulk_group "
                "[%0, {%1, %2, %3}], [%4];"
                :: "l"(&tmap), "r"(0), "r"(0), "r"(row), "r"(sbase) : "memory");
            asm volatile("cp.async.bulk.commit_group;" ::: "memory");
            // <=1 group pending: the other buffer is free for ii+1
            asm volatile("cp.async.bulk.wait_group.read 1;" ::: "memory");
        }
        __syncthreads();
    }

    if (tid == 0)
        asm volatile("cp.async.bulk.wait_group 0;" ::: "memory");
}

// ---------------------------------------------------------------------------
typedef CUresult (*EncodeFn)(
    CUtensorMap*, CUtensorMapDataType, cuuint32_t, void*,
    const cuuint64_t*, const cuuint64_t*, const cuuint32_t*, const cuuint32_t*,
    CUtensorMapInterleave, CUtensorMapSwizzle, CUtensorMapL2promotion,
    CUtensorMapFloatOOBfill);

extern "C" void kernel_launch(void* const* d_in, const int* in_sizes, int n_in,
                              void* d_out, int out_size)
{
    const float* x   = (const float*)d_in[0];
    const float* lnw = (const float*)d_in[1];
    const float* lnb = (const float*)d_in[2];
    const float* pw  = (const float*)d_in[3];
    const float* pb  = (const float*)d_in[4];
    const float* ow  = (const float*)d_in[5];
    const float* ob  = (const float*)d_in[6];

    // Output viewed as [row = i*L+j : 1M][chunk : 4][32 f32]; one 32KB box/tile.
    CUtensorMap tmap;
    {
        void* fn = nullptr;
        cudaDriverEntryPointQueryResult qr;
        cudaGetDriverEntryPoint("cuTensorMapEncodeTiled", &fn,
                                cudaEnableDefault, &qr);
        EncodeFn enc = (EncodeFn)fn;
        cuuint64_t dims[3]    = {32, 4, (cuuint64_t)L_SEQ * L_SEQ};
        cuuint64_t strides[2] = {128, 512};          // bytes
        cuuint32_t box[3]     = {32, 4, JT};
        cuuint32_t es[3]      = {1, 1, 1};
        enc(&tmap, CU_TENSOR_MAP_DATA_TYPE_FLOAT32, 3, d_out,
            dims, strides, box, es,
            CU_TENSOR_MAP_INTERLEAVE_NONE, CU_TENSOR_MAP_SWIZZLE_128B,
            CU_TENSOR_MAP_L2_PROMOTION_NONE, CU_TENSOR_MAP_FLOAT_OOB_FILL_NONE);
    }

    cudaFuncSetAttribute(phase2_kernel,
                         cudaFuncAttributeMaxDynamicSharedMemorySize, SMEM2_BYTES);

    phase1_kernel<<<dim3(L_SEQ / R1, 2), 256>>>(x, lnw, lnb, pw, pb, ow);
    phase2_kernel<<<dim3(L_SEQ / JT, L_SEQ / I_PER_CTA), 256, SMEM2_BYTES>>>(
        tmap, ow, ob);
}